// round 10
// baseline (speedup 1.0000x reference)
#include <cuda_runtime.h>
#include <cuda_fp16.h>
#include <cstdint>
#include <cstddef>

// ============================================================
// out[16384,4096] = X[16384,4096] @ W[4096,4096]^T
// W = (w_pos>0) - (w_neg>0)  in {-1,0,+1}  (exact in fp16)
// CTA 128x128xK64, 4 warps (2x2), warp tile 64x64, 2-stage double
// buffer (64KB) -> 3 CTAs/SM at <=170 regs. A-duplication halved vs
// 64x32: smem crossbar drops below tensor-pipe time; 3 CTAs cover
// barrier bubbles.
// ============================================================
#define M_TOTAL 16384
#define N_TOTAL 4096
#define K_TOTAL 4096

#define TILE_M 128
#define TILE_N 128
#define TILE_K 64
#define STAGES 2
#define NCHUNK (K_TOTAL / TILE_K)         // 64
#define N_TILES (N_TOTAL / TILE_N)        // 32
#define M_TILES (M_TOTAL / TILE_M)        // 128

#define A_BYTES (TILE_M * TILE_K * 2)     // 16384
#define B_BYTES (TILE_N * TILE_K * 2)     // 16384
#define STAGE_BYTES (A_BYTES + B_BYTES)   // 32768
#define SMEM_TOTAL (STAGES * STAGE_BYTES) // 65536

__device__ __align__(128) __half g_W[(size_t)N_TOTAL * K_TOTAL];  // [N,K] 32 MB
__device__ __align__(128) __half g_X[(size_t)M_TOTAL * K_TOTAL];  // [M,K] 128 MB

// ============================================================
// Base-ISA PTX helpers
// ============================================================
__device__ __forceinline__ uint32_t smem_u32(const void* p) {
    uint32_t a;
    asm("{ .reg .u64 t; cvta.to.shared.u64 t, %1; cvt.u32.u64 %0, t; }"
        : "=r"(a) : "l"(p));
    return a;
}

#define CP_ASYNC16(dst_u32, src_ptr) \
    asm volatile("cp.async.cg.shared.global [%0], [%1], 16;" \
                 :: "r"(dst_u32), "l"(src_ptr) : "memory")
#define CP_COMMIT() asm volatile("cp.async.commit_group;" ::: "memory")
#define CP_WAIT(n)  asm volatile("cp.async.wait_group %0;" :: "n"(n) : "memory")

__device__ __forceinline__ void ldsm4(uint32_t* r, uint32_t addr) {
    asm volatile("ldmatrix.sync.aligned.m8n8.x4.shared.b16 {%0,%1,%2,%3}, [%4];"
                 : "=r"(r[0]), "=r"(r[1]), "=r"(r[2]), "=r"(r[3]) : "r"(addr));
}

__device__ __forceinline__ void mma16816(float* d, const uint32_t* a,
                                         uint32_t b0, uint32_t b1) {
    asm volatile(
        "mma.sync.aligned.m16n8k16.row.col.f32.f16.f16.f32 "
        "{%0,%1,%2,%3}, {%4,%5,%6,%7}, {%8,%9}, {%0,%1,%2,%3};"
        : "+f"(d[0]), "+f"(d[1]), "+f"(d[2]), "+f"(d[3])
        : "r"(a[0]), "r"(a[1]), "r"(a[2]), "r"(a[3]), "r"(b0), "r"(b1));
}

__device__ __forceinline__ uint32_t sw128(uint32_t off) {
    return off ^ ((off >> 3) & 0x70u);
}

// ============================================================
// Merged prep kernel
// ============================================================
#define N4X ((M_TOTAL * K_TOTAL) / 4)
#define N4W ((N_TOTAL * K_TOTAL) / 4)
#define XB  (N4X / 256)
#define WB  (N4W / 256)

__global__ void k_prep(const float4* __restrict__ x,
                       const float4* __restrict__ wp,
                       const float4* __restrict__ wn) {
    int i = blockIdx.x * 256 + threadIdx.x;
    if (i < N4X) {
        float4 v = x[i];
        __half2* dst = (__half2*)g_X;
        dst[2 * i + 0] = __floats2half2_rn(v.x, v.y);
        dst[2 * i + 1] = __floats2half2_rn(v.z, v.w);
    } else {
        int j = i - N4X;
        float4 p = wp[j];
        float4 n = wn[j];
        float a = (float)((p.x > 0.f) - (n.x > 0.f));
        float b = (float)((p.y > 0.f) - (n.y > 0.f));
        float c = (float)((p.z > 0.f) - (n.z > 0.f));
        float d = (float)((p.w > 0.f) - (n.w > 0.f));
        __half2* dst = (__half2*)g_W;
        dst[2 * j + 0] = __floats2half2_rn(a, b);
        dst[2 * j + 1] = __floats2half2_rn(c, d);
    }
}

// ============================================================
// GEMM
// ============================================================
// Stage fill with 128 threads: thread t -> A row t (8 x 16B) + B row t (8 x 16B).
__device__ __forceinline__ void issue_tile_loads(
    uint32_t smem_base, int s, int kc, int m0, int n0, int tid)
{
    uint32_t sa = smem_base + (uint32_t)s * STAGE_BYTES;
    uint32_t sb = sa + A_BYTES;
    const char* srcA = (const char*)(g_X + (size_t)(m0 + tid) * K_TOTAL + kc * TILE_K);
    const char* srcB = (const char*)(g_W + (size_t)(n0 + tid) * K_TOTAL + kc * TILE_K);
    uint32_t rb = (uint32_t)tid * 128u;
    #pragma unroll
    for (int c = 0; c < 8; c++) {
        uint32_t off = rb + (uint32_t)c * 16u;
        uint32_t sw = sw128(off);
        CP_ASYNC16(sa + sw, srcA + c * 16);
        CP_ASYNC16(sb + sw, srcB + c * 16);
    }
}

__global__ void __launch_bounds__(128, 3) plinear_gemm(float* __restrict__ out) {
    extern __shared__ char smem[];
    uint32_t smem_base = smem_u32(smem);
    const int tid = threadIdx.x;
    const int wid = tid >> 5;
    const int lid = tid & 31;

    // N-fast: wave shares X tiles, W (32MB fp16) stays L2-resident
    const int nt = blockIdx.x & (N_TILES - 1);
    const int mt = blockIdx.x >> 5;
    const int m0 = mt * TILE_M;
    const int n0 = nt * TILE_N;

    // warp grid 2(M) x 2(N): warp tile 64 x 64
    const int mwarp = (wid >> 1) * 64;
    const int nwarp = (wid & 1) * 64;

    float acc[4][8][4];
    #pragma unroll
    for (int i = 0; i < 4; i++)
        #pragma unroll
        for (int j = 0; j < 8; j++)
            #pragma unroll
            for (int c = 0; c < 4; c++) acc[i][j][c] = 0.f;

    // Pre-swizzled ldmatrix base offsets; XOR k-step advance (col bits 5-6
    // of the pre-swizzle offset are zero -> sw128(off+kb) == sw128(off)^kb).
    const int a_r = (lid & 7) + (((lid >> 3) & 1) << 3);
    const int a_c = (lid >> 4) << 4;
    const int b_r = (lid & 7) + ((lid >> 4) << 3);
    const int b_c = ((lid >> 3) & 1) << 4;
    uint32_t aoff[4], boff[4];
    #pragma unroll
    for (int i = 0; i < 4; i++)
        aoff[i] = sw128((uint32_t)(mwarp + i * 16 + a_r) * 128u + a_c);
    #pragma unroll
    for (int j = 0; j < 4; j++)
        boff[j] = sw128((uint32_t)(nwarp + j * 16 + b_r) * 128u + b_c) + A_BYTES;

    // Prologue: stage 0 <- chunk 0
    issue_tile_loads(smem_base, 0, 0, m0, n0, tid); CP_COMMIT();

    #pragma unroll 1
    for (int kc = 0; kc < NCHUNK; kc++) {
        CP_WAIT(0);          // chunk kc fully arrived (only it is outstanding)
        __syncthreads();     // writes visible + prior reads of other buffer done

        if (kc + 1 < NCHUNK)
            issue_tile_loads(smem_base, (kc + 1) & 1, kc + 1, m0, n0, tid);
        CP_COMMIT();

        const uint32_t sa = smem_base + (uint32_t)(kc & 1) * STAGE_BYTES;

        #pragma unroll
        for (int ks = 0; ks < 4; ks++) {
            const uint32_t kb = (uint32_t)ks * 32u;  // bits 5-6 only
            uint32_t a[4][4], b[4][4];
            #pragma unroll
            for (int i = 0; i < 4; i++) ldsm4(a[i], sa + (aoff[i] ^ kb));
            #pragma unroll
            for (int j = 0; j < 4; j++) ldsm4(b[j], sa + (boff[j] ^ kb));
            #pragma unroll
            for (int i = 0; i < 4; i++)
                #pragma unroll
                for (int j = 0; j < 4; j++) {
                    mma16816(acc[i][2 * j + 0], a[i], b[j][0], b[j][1]);
                    mma16816(acc[i][2 * j + 1], a[i], b[j][2], b[j][3]);
                }
        }
    }

    // Epilogue
    {
        const int g  = lid >> 2;
        const int t2 = (lid & 3) * 2;
        #pragma unroll
        for (int i = 0; i < 4; i++) {
            float* r0 = out + (size_t)(m0 + mwarp + i * 16 + g) * N_TOTAL + n0 + nwarp + t2;
            float* r1 = r0 + 8 * N_TOTAL;
            #pragma unroll
            for (int j = 0; j < 8; j++) {
                *(float2*)(r0 + j * 8) = make_float2(acc[i][j][0], acc[i][j][1]);
                *(float2*)(r1 + j * 8) = make_float2(acc[i][j][2], acc[i][j][3]);
            }
        }
    }
}

// ============================================================
// Launch
// ============================================================
extern "C" void kernel_launch(void* const* d_in, const int* in_sizes, int n_in,
                              void* d_out, int out_size) {
    const float* x  = (const float*)d_in[0];
    const float* wp = (const float*)d_in[1];
    const float* wn = (const float*)d_in[2];
    float* out = (float*)d_out;

    cudaFuncSetAttribute(plinear_gemm,
                         cudaFuncAttributeMaxDynamicSharedMemorySize, SMEM_TOTAL);

    k_prep<<<XB + WB, 256>>>((const float4*)x, (const float4*)wp, (const float4*)wn);
    plinear_gemm<<<M_TILES * N_TILES, 128, SMEM_TOTAL>>>(out);
}

// round 11
// speedup vs baseline: 1.9467x; 1.9467x over previous
#include <cuda_runtime.h>
#include <cuda_fp16.h>
#include <cstdint>
#include <cstddef>

// ============================================================
// out[16384,4096] = X[16384,4096] @ W[4096,4096]^T
// W = (w_pos>0) - (w_neg>0) in {-1,0,+1}
// R7 base (CTA 128x128, 8 warps 2x4, warp tile 64x32, 16 warps/SM,
// 2 CTAs/SM) but B never touches smem: ternary W packed as PRMT
// selectors (8b/code); each B fragment reg = one prmt.b32 vs LUT.
// Crossbar: A-only (reads 4x dup + writes) ~640 wf/chunk vs 1024.
// ============================================================
#define M_TOTAL 16384
#define N_TOTAL 4096
#define K_TOTAL 4096

#define TILE_M 128
#define TILE_N 128
#define TILE_K 64
#define STAGES 3
#define NCHUNK (K_TOTAL / TILE_K)         // 64
#define N_TILES (N_TOTAL / TILE_N)        // 32
#define M_TILES (M_TOTAL / TILE_M)        // 128

#define A_BYTES (TILE_M * TILE_K * 2)     // 16384 (A only)
#define STAGE_BYTES A_BYTES
#define SMEM_TOTAL (STAGES * STAGE_BYTES) // 49152

// fp16 LUT for PRMT: byte0=0xBC,byte1=0x00,byte2=0x3C,byte3=0x00
// code c in {0,1,2} -> hi-byte of fp16(c-1); nibble 3 selects 0x00.
#define B_LUT 0x003C00BCu

__device__ __align__(128) __half   g_X[(size_t)M_TOTAL * K_TOTAL];       // 128 MB
// Selector table: [n>>3][kword(256)][(n&7)*4 + t] u32; each u32 = two
// sel16 covering codes (k=16kw+2t,+1) and (k=16kw+8+2t,+1) for row n.
#define W2_WORDS ((size_t)(N_TOTAL / 8) * (K_TOTAL / 16) * 32)           // 4194304
__device__ __align__(128) uint32_t g_W2[W2_WORDS];                       // 16 MB

// ============================================================
// PTX helpers (base ISA)
// ============================================================
__device__ __forceinline__ uint32_t smem_u32(const void* p) {
    uint32_t a;
    asm("{ .reg .u64 t; cvta.to.shared.u64 t, %1; cvt.u32.u64 %0, t; }"
        : "=r"(a) : "l"(p));
    return a;
}

#define CP_ASYNC16(dst_u32, src_ptr) \
    asm volatile("cp.async.cg.shared.global [%0], [%1], 16;" \
                 :: "r"(dst_u32), "l"(src_ptr) : "memory")
#define CP_COMMIT() asm volatile("cp.async.commit_group;" ::: "memory")
#define CP_WAIT(n)  asm volatile("cp.async.wait_group %0;" :: "n"(n) : "memory")

__device__ __forceinline__ void ldsm4(uint32_t* r, uint32_t addr) {
    asm volatile("ldmatrix.sync.aligned.m8n8.x4.shared.b16 {%0,%1,%2,%3}, [%4];"
                 : "=r"(r[0]), "=r"(r[1]), "=r"(r[2]), "=r"(r[3]) : "r"(addr));
}

__device__ __forceinline__ void mma16816(float* d, const uint32_t* a,
                                         uint32_t b0, uint32_t b1) {
    asm volatile(
        "mma.sync.aligned.m16n8k16.row.col.f32.f16.f16.f32 "
        "{%0,%1,%2,%3}, {%4,%5,%6,%7}, {%8,%9}, {%0,%1,%2,%3};"
        : "+f"(d[0]), "+f"(d[1]), "+f"(d[2]), "+f"(d[3])
        : "r"(a[0]), "r"(a[1]), "r"(a[2]), "r"(a[3]), "r"(b0), "r"(b1));
}

__device__ __forceinline__ uint32_t prmt_lut(uint32_t sel) {
    uint32_t d;
    asm("prmt.b32 %0, %1, %2, %3;" : "=r"(d) : "r"(B_LUT), "r"(0u), "r"(sel));
    return d;
}

__device__ __forceinline__ uint32_t sw128(uint32_t off) {
    return off ^ ((off >> 3) & 0x70u);
}

// ============================================================
// Merged prep: blocks [0,XB) convert x->fp16; [XB,XB+W2B) build table
// ============================================================
#define N4X ((M_TOTAL * K_TOTAL) / 4)     // 16777216
#define XB  (N4X / 256)                   // 65536
#define W2B ((int)(W2_WORDS / 256))       // 16384

__global__ void k_prep(const float4* __restrict__ x,
                       const float* __restrict__ wp,
                       const float* __restrict__ wn) {
    int bi = blockIdx.x;
    if (bi < XB) {
        int i = bi * 256 + threadIdx.x;
        float4 v = x[i];
        __half2* dst = (__half2*)g_X;
        dst[2 * i + 0] = __floats2half2_rn(v.x, v.y);
        dst[2 * i + 1] = __floats2half2_rn(v.z, v.w);
    } else {
        int id = (bi - XB) * 256 + threadIdx.x;   // u32 index into g_W2
        int s     = id & 31;          // (n&7)*4 + t
        int kword = (id >> 5) & 255;
        int blk   = id >> 13;
        int n  = blk * 8 + (s >> 2);
        int t  = s & 3;
        int kb = kword * 16 + t * 2;
        const float* wpr = wp + (size_t)n * K_TOTAL;
        const float* wnr = wn + (size_t)n * K_TOTAL;
        uint32_t c0 = (uint32_t)((wpr[kb + 0] > 0.f) - (wnr[kb + 0] > 0.f) + 1);
        uint32_t c1 = (uint32_t)((wpr[kb + 1] > 0.f) - (wnr[kb + 1] > 0.f) + 1);
        uint32_t c2 = (uint32_t)((wpr[kb + 8] > 0.f) - (wnr[kb + 8] > 0.f) + 1);
        uint32_t c3 = (uint32_t)((wpr[kb + 9] > 0.f) - (wnr[kb + 9] > 0.f) + 1);
        g_W2[id] = 0x03030303u | (c0 << 4) | (c1 << 12) | (c2 << 20) | (c3 << 28);
    }
}

// ============================================================
// GEMM
// ============================================================
// A-only stage fill (256 threads): thread t -> row t>>1, 4 x 16B.
__device__ __forceinline__ void issue_tile_loads(
    uint32_t smem_base, int s, int kc, int m0, int tid)
{
    uint32_t sa = smem_base + (uint32_t)s * STAGE_BYTES;
    const int row = tid >> 1;
    const int c0  = (tid & 1) * 4;
    const char* srcA = (const char*)(g_X + (size_t)(m0 + row) * K_TOTAL + kc * TILE_K);
    uint32_t rb = (uint32_t)row * 128u;
    #pragma unroll
    for (int c = 0; c < 4; c++) {
        uint32_t off = rb + (uint32_t)(c0 + c) * 16u;
        CP_ASYNC16(sa + sw128(off), srcA + (c0 + c) * 16);
    }
}

__global__ void __launch_bounds__(256, 2) plinear_gemm(float* __restrict__ out) {
    extern __shared__ char smem[];
    uint32_t smem_base = smem_u32(smem);
    const int tid = threadIdx.x;
    const int wid = tid >> 5;
    const int lid = tid & 31;

    // N-fast: wave shares X tiles; W2 table (16MB) L2-resident
    const int nt = blockIdx.x & (N_TILES - 1);
    const int mt = blockIdx.x >> 5;
    const int m0 = mt * TILE_M;
    const int n0 = nt * TILE_N;

    // warp grid 2(M) x 4(N): warp tile 64 x 32
    const int mwarp = (wid >> 2) * 64;
    const int nwarp = (wid & 3) * 32;

    float acc[4][4][4];
    #pragma unroll
    for (int i = 0; i < 4; i++)
        #pragma unroll
        for (int j = 0; j < 4; j++)
            #pragma unroll
            for (int c = 0; c < 4; c++) acc[i][j][c] = 0.f;

    // A ldmatrix base offsets (pre-swizzled); XOR k-step advance.
    const int a_r = (lid & 7) + (((lid >> 3) & 1) << 3);
    const int a_c = (lid >> 4) << 4;
    uint32_t aoff[4];
    #pragma unroll
    for (int i = 0; i < 4; i++)
        aoff[i] = sw128((uint32_t)(mwarp + i * 16 + a_r) * 128u + a_c);

    // W2 per-thread base: rows (n0+nwarp+d*8), d = j*2 + h (h: n-halves)
    // word(d, kw) = wbase[d*8192 + kw*32]
    const uint32_t* wbase =
        g_W2 + ((size_t)((n0 + nwarp) >> 3) * 256) * 32 + lid;

    // Prologue: A stages 0..1
    issue_tile_loads(smem_base, 0, 0, m0, tid); CP_COMMIT();
    issue_tile_loads(smem_base, 1, 1, m0, tid); CP_COMMIT();

    uint32_t a[2][4][4];
    uint32_t w[2][4];        // [pipeline][d=j*2+h]
    int s_cur = 0;

    #pragma unroll 1
    for (int kc = 0; kc < NCHUNK; kc++) {
        // W words for k-step 0 of this chunk (independent of smem/barrier)
        {
            const int kw = kc * 4;
            #pragma unroll
            for (int d = 0; d < 4; d++) w[0][d] = wbase[d * 8192 + kw * 32];
        }

        CP_WAIT(1);          // A stage kc arrived
        __syncthreads();     // + prior reads of reused stage complete

        const int pf = kc + 2;
        if (pf < NCHUNK) {
            int sp = s_cur + 2; if (sp >= STAGES) sp -= STAGES;
            issue_tile_loads(smem_base, sp, pf, m0, tid);
        }
        CP_COMMIT();

        const uint32_t sa = smem_base + (uint32_t)s_cur * STAGE_BYTES;
        if (++s_cur == STAGES) s_cur = 0;

        // A k-step 0 fragments
        #pragma unroll
        for (int i = 0; i < 4; i++) ldsm4(a[0][i], sa + aoff[i]);

        #pragma unroll
        for (int ks = 0; ks < 4; ks++) {
            const int cur = ks & 1, nxt = cur ^ 1;
            if (ks < 3) {
                const int kw = kc * 4 + ks + 1;
                #pragma unroll
                for (int d = 0; d < 4; d++) w[nxt][d] = wbase[d * 8192 + kw * 32];
                const uint32_t kb = (uint32_t)(ks + 1) * 32u;  // bits 5-6 only
                #pragma unroll
                for (int i = 0; i < 4; i++) ldsm4(a[nxt][i], sa + (aoff[i] ^ kb));
            }
            // Expand B fragments: reg = prmt(LUT, sel16)
            uint32_t b[2][4];
            #pragma unroll
            for (int j = 0; j < 2; j++) {
                uint32_t w0 = w[cur][j * 2 + 0];
                uint32_t w1 = w[cur][j * 2 + 1];
                b[j][0] = prmt_lut(w0);
                b[j][1] = prmt_lut(w0 >> 16);
                b[j][2] = prmt_lut(w1);
                b[j][3] = prmt_lut(w1 >> 16);
            }
            #pragma unroll
            for (int i = 0; i < 4; i++)
                #pragma unroll
                for (int j = 0; j < 2; j++) {
                    mma16816(acc[i][2 * j + 0], a[cur][i], b[j][0], b[j][1]);
                    mma16816(acc[i][2 * j + 1], a[cur][i], b[j][2], b[j][3]);
                }
        }
    }

    // Epilogue
    {
        const int g  = lid >> 2;
        const int t2 = (lid & 3) * 2;
        #pragma unroll
        for (int i = 0; i < 4; i++) {
            float* r0 = out + (size_t)(m0 + mwarp + i * 16 + g) * N_TOTAL + n0 + nwarp + t2;
            float* r1 = r0 + 8 * N_TOTAL;
            #pragma unroll
            for (int j = 0; j < 4; j++) {
                *(float2*)(r0 + j * 8) = make_float2(acc[i][j][0], acc[i][j][1]);
                *(float2*)(r1 + j * 8) = make_float2(acc[i][j][2], acc[i][j][3]);
            }
        }
    }
}

// ============================================================
// Launch
// ============================================================
extern "C" void kernel_launch(void* const* d_in, const int* in_sizes, int n_in,
                              void* d_out, int out_size) {
    const float* x  = (const float*)d_in[0];
    const float* wp = (const float*)d_in[1];
    const float* wn = (const float*)d_in[2];
    float* out = (float*)d_out;

    cudaFuncSetAttribute(plinear_gemm,
                         cudaFuncAttributeMaxDynamicSharedMemorySize, SMEM_TOTAL);

    k_prep<<<XB + W2B, 256>>>((const float4*)x, wp, wn);
    plinear_gemm<<<M_TILES * N_TILES, 256, SMEM_TOTAL>>>(out);
}